// round 11
// baseline (speedup 1.0000x reference)
#include <cuda_runtime.h>

#define IN_F   4096
#define OUT_F  11008
#define TOKENS 8

#define THREADS 512
#define WARPS_PER_BLOCK 16
#define GRID 148

#define NPAIR (OUT_F / 2)                 // 5504 row pairs
#define KCHUNK 2048                       // columns per K-half
#define CHUNK_F4 (KCHUNK / 4)             // 512 float4
#define PAIR_SLOTS (WARPS_PER_BLOCK / 2)  // 8 pairs per block per round
#define PAIRS_PER_ROUND (GRID * PAIR_SLOTS)   // 1184
#define ROUNDS ((NPAIR + PAIRS_PER_ROUND - 1) / PAIRS_PER_ROUND)  // 5

// smem: x[8][4096] | sumx[8] | scratch[2][8 slots][16]
#define SMEM_FLOATS (TOKENS * IN_F + TOKENS + 2 * PAIR_SLOTS * 16)
#define SMEM_BYTES  (SMEM_FLOATS * 4)

// 64-thread named barrier, one per pair-slot (ids 1..8)
#define SLOT_BAR(slot) asm volatile("bar.sync %0, 64;" :: "r"(1 + (slot)) : "memory")

__global__ __launch_bounds__(THREADS, 1)
void dql_fused(const float* __restrict__ x,
               const float* __restrict__ W,
               const int*   __restrict__ Q,
               const float* __restrict__ scales,
               const float* __restrict__ zp,
               const float* __restrict__ bias,
               float*       __restrict__ out) {
    extern __shared__ float xs[];                 // [TOKENS][IN_F]
    float* sumx    = xs + TOKENS * IN_F;          // [8]
    float* scratch = sumx + TOKENS;               // [2][8][16]

    // ---- stage x into shared (128 KB), vectorized ----
    {
        const float4* x4 = (const float4*)x;
        float4* xs4w = (float4*)xs;
        #pragma unroll
        for (int i = threadIdx.x; i < TOKENS * IN_F / 4; i += THREADS)
            xs4w[i] = x4[i];
    }
    __syncthreads();

    const int warp  = threadIdx.x >> 5;
    const int lane  = threadIdx.x & 31;

    // ---- in-kernel sumx: warp t reduces token t from shared ----
    if (warp < TOKENS) {
        float s = 0.f;
        #pragma unroll 4
        for (int i = lane; i < IN_F; i += 32) s += xs[warp * IN_F + i];
        #pragma unroll
        for (int off = 16; off; off >>= 1) s += __shfl_xor_sync(0xffffffffu, s, off);
        if (lane == 0) sumx[warp] = s;
    }
    __syncthreads();   // sumx visible to everyone; last block-wide barrier

    const int slot  = warp >> 1;        // 0..7 : pair slot within block
    const int khalf = warp & 1;         // 0/1  : K half
    const float4* xs4 = (const float4*)xs;

    for (int r = 0; r < ROUNDS; ++r) {
        const int pair = r * PAIRS_PER_ROUND + blockIdx.x * PAIR_SLOTS + slot;
        const bool active = (pair < NPAIR);   // uniform across the 64-thread slot
        float* buf = scratch + (r & 1) * (PAIR_SLOTS * 16) + slot * 16;

        float v1 = 0.f;
        int o0 = 0;
        float s0 = 0.f, s1 = 0.f;

        if (active) {
            o0 = pair << 1;
            const int o1 = o0 + 1;
            s0 = scales[o0];
            s1 = scales[o1];

            const float4* w0 = (const float4*)(W + (size_t)o0 * IN_F + khalf * KCHUNK);
            const float4* w1 = (const float4*)(W + (size_t)o1 * IN_F + khalf * KCHUNK);
            const int4*   q0 = (const int4*)(Q + (size_t)o0 * IN_F + khalf * KCHUNK);
            const int4*   q1 = (const int4*)(Q + (size_t)o1 * IN_F + khalf * KCHUNK);
            const float4* xb = xs4 + khalf * CHUNK_F4;

            float acc0[TOKENS], acc1[TOKENS];
            #pragma unroll
            for (int t = 0; t < TOKENS; t++) { acc0[t] = 0.f; acc1[t] = 0.f; }

            // 512 float4 per K-half / 32 lanes = 16 iterations; unroll 4
            #pragma unroll 4
            for (int it = 0; it < CHUNK_F4 / 32; ++it) {
                const int c = it * 32 + lane;
                float4 wa = w0[c];
                float4 wb = w1[c];
                int4   qa = q0[c];
                int4   qb = q1[c];

                float4 fa, fb;
                fa.x = fmaf(s0, (float)qa.x, wa.x);
                fa.y = fmaf(s0, (float)qa.y, wa.y);
                fa.z = fmaf(s0, (float)qa.z, wa.z);
                fa.w = fmaf(s0, (float)qa.w, wa.w);
                fb.x = fmaf(s1, (float)qb.x, wb.x);
                fb.y = fmaf(s1, (float)qb.y, wb.y);
                fb.z = fmaf(s1, (float)qb.z, wb.z);
                fb.w = fmaf(s1, (float)qb.w, wb.w);

                #pragma unroll
                for (int t = 0; t < TOKENS; t++) {
                    float4 xv = xb[t * (IN_F / 4) + c];
                    acc0[t] = fmaf(fa.x, xv.x, acc0[t]);
                    acc0[t] = fmaf(fa.y, xv.y, acc0[t]);
                    acc0[t] = fmaf(fa.z, xv.z, acc0[t]);
                    acc0[t] = fmaf(fa.w, xv.w, acc0[t]);
                    acc1[t] = fmaf(fb.x, xv.x, acc1[t]);
                    acc1[t] = fmaf(fb.y, xv.y, acc1[t]);
                    acc1[t] = fmaf(fb.z, xv.z, acc1[t]);
                    acc1[t] = fmaf(fb.w, xv.w, acc1[t]);
                }
            }

            // Segmented fold: 16 values summed across 32 lanes in 31 shfls.
            // Result on even lanes: r = lane bit4, t = lane bits 3..1.
            float v16[16];
            #pragma unroll
            for (int t = 0; t < TOKENS; t++) { v16[2*t] = acc0[t]; v16[2*t+1] = acc1[t]; }
            #pragma unroll
            for (int i = 0; i < 16; i++) v16[i] += __shfl_xor_sync(0xffffffffu, v16[i], 16);
            float v8[8];
            #pragma unroll
            for (int i = 0; i < 8; i++) v8[i] = (lane & 16) ? v16[2*i+1] : v16[2*i];
            #pragma unroll
            for (int i = 0; i < 8; i++) v8[i] += __shfl_xor_sync(0xffffffffu, v8[i], 8);
            float v4[4];
            #pragma unroll
            for (int i = 0; i < 4; i++) v4[i] = (lane & 8) ? v8[2*i+1] : v8[2*i];
            #pragma unroll
            for (int i = 0; i < 4; i++) v4[i] += __shfl_xor_sync(0xffffffffu, v4[i], 4);
            float v2[2];
            #pragma unroll
            for (int i = 0; i < 2; i++) v2[i] = (lane & 4) ? v4[2*i+1] : v4[2*i];
            #pragma unroll
            for (int i = 0; i < 2; i++) v2[i] += __shfl_xor_sync(0xffffffffu, v2[i], 2);
            v1 = (lane & 2) ? v2[1] : v2[0];
            v1 += __shfl_xor_sync(0xffffffffu, v1, 1);

            // odd warp deposits its 16 partials into this round's buffer
            if (khalf == 1 && !(lane & 1)) {
                buf[lane >> 1] = v1;
            }
        }

        SLOT_BAR(slot);   // pair-local: producer's deposit visible to consumer

        if (active && khalf == 0 && !(lane & 1)) {
            int rr = (lane >> 4) & 1;
            int t  = ((lane >> 3) & 1) | (((lane >> 2) & 1) << 1) | (((lane >> 1) & 1) << 2);
            int o  = o0 + rr;
            float sr = rr ? s1 : s0;
            float total = v1 + buf[lane >> 1];
            out[t * OUT_F + o] = total + fmaf(-sr * zp[o], sumx[t], bias[o]);
        }
        // no second barrier: next round writes the other scratch buffer, and the
        // round-(r+1) SLOT_BAR fences the round-(r+2) rewrite of this buffer.
    }
}

extern "C" void kernel_launch(void* const* d_in, const int* in_sizes, int n_in,
                              void* d_out, int out_size) {
    const float* x      = (const float*)d_in[0];
    const float* W      = (const float*)d_in[1];
    const int*   Q      = (const int*)d_in[2];
    const float* scales = (const float*)d_in[3];
    const float* zp     = (const float*)d_in[4];
    const float* bias   = (const float*)d_in[5];
    float* out = (float*)d_out;

    cudaFuncSetAttribute(dql_fused, cudaFuncAttributeMaxDynamicSharedMemorySize,
                         SMEM_BYTES);

    dql_fused<<<GRID, THREADS, SMEM_BYTES>>>(x, W, Q, scales, zp, bias, out);
}

// round 12
// speedup vs baseline: 1.1313x; 1.1313x over previous
#include <cuda_runtime.h>

#define IN_F   4096
#define OUT_F  11008
#define TOKENS 8

#define THREADS 512
#define WARPS_PER_BLOCK 16
#define GRID 148

#define NPAIR (OUT_F / 2)                 // 5504 row pairs
#define KCHUNK 2048                       // columns per K-half
#define CHUNK_F4 (KCHUNK / 4)             // 512 float4
#define PAIR_SLOTS (WARPS_PER_BLOCK / 2)  // 8 pairs per block per round
#define PAIRS_PER_ROUND (GRID * PAIR_SLOTS)   // 1184
#define ROUNDS ((NPAIR + PAIRS_PER_ROUND - 1) / PAIRS_PER_ROUND)  // 5

// smem: x[8][4096] | sumx[8] | scratch[2][8 slots][16]
#define SMEM_FLOATS (TOKENS * IN_F + TOKENS + 2 * PAIR_SLOTS * 16)
#define SMEM_BYTES  (SMEM_FLOATS * 4)

__global__ __launch_bounds__(THREADS, 1)
void dql_fused(const float* __restrict__ x,
               const float* __restrict__ W,
               const int*   __restrict__ Q,
               const float* __restrict__ scales,
               const float* __restrict__ zp,
               const float* __restrict__ bias,
               float*       __restrict__ out) {
    extern __shared__ float xs[];                 // [TOKENS][IN_F]
    float* sumx    = xs + TOKENS * IN_F;          // [8]
    float* scratch = sumx + TOKENS;               // [2][8][16]

    // ---- stage x into shared (128 KB), vectorized ----
    {
        const float4* x4 = (const float4*)x;
        float4* xs4w = (float4*)xs;
        #pragma unroll
        for (int i = threadIdx.x; i < TOKENS * IN_F / 4; i += THREADS)
            xs4w[i] = x4[i];
    }
    __syncthreads();

    const int warp  = threadIdx.x >> 5;
    const int lane  = threadIdx.x & 31;

    // ---- in-kernel sumx: warp t reduces token t from shared ----
    if (warp < TOKENS) {
        float s = 0.f;
        #pragma unroll 4
        for (int i = lane; i < IN_F; i += 32) s += xs[warp * IN_F + i];
        #pragma unroll
        for (int off = 16; off; off >>= 1) s += __shfl_xor_sync(0xffffffffu, s, off);
        if (lane == 0) sumx[warp] = s;
    }
    // sumx visibility is ordered by round 0's __syncthreads below

    const int slot  = warp >> 1;        // 0..7 : pair slot within block
    const int khalf = warp & 1;         // 0/1  : K half
    const float4* xs4 = (const float4*)xs;

    for (int r = 0; r < ROUNDS; ++r) {
        const int pair = r * PAIRS_PER_ROUND + blockIdx.x * PAIR_SLOTS + slot;
        const bool active = (pair < NPAIR);
        float* buf = scratch + (r & 1) * (PAIR_SLOTS * 16) + slot * 16;

        float v1 = 0.f;
        int o0 = 0;
        float s0 = 0.f, s1 = 0.f;

        if (active) {
            o0 = pair << 1;
            const int o1 = o0 + 1;
            s0 = scales[o0];
            s1 = scales[o1];

            const float4* w0 = (const float4*)(W + (size_t)o0 * IN_F + khalf * KCHUNK);
            const float4* w1 = (const float4*)(W + (size_t)o1 * IN_F + khalf * KCHUNK);
            const int4*   q0 = (const int4*)(Q + (size_t)o0 * IN_F + khalf * KCHUNK);
            const int4*   q1 = (const int4*)(Q + (size_t)o1 * IN_F + khalf * KCHUNK);
            const float4* xb = xs4 + khalf * CHUNK_F4;

            float acc0[TOKENS], acc1[TOKENS];
            #pragma unroll
            for (int t = 0; t < TOKENS; t++) { acc0[t] = 0.f; acc1[t] = 0.f; }

            // 512 float4 per K-half / 32 lanes = 16 iterations; unroll 4
            #pragma unroll 4
            for (int it = 0; it < CHUNK_F4 / 32; ++it) {
                const int c = it * 32 + lane;
                float4 wa = w0[c];
                float4 wb = w1[c];
                int4   qa = q0[c];
                int4   qb = q1[c];

                float4 fa, fb;
                fa.x = fmaf(s0, (float)qa.x, wa.x);
                fa.y = fmaf(s0, (float)qa.y, wa.y);
                fa.z = fmaf(s0, (float)qa.z, wa.z);
                fa.w = fmaf(s0, (float)qa.w, wa.w);
                fb.x = fmaf(s1, (float)qb.x, wb.x);
                fb.y = fmaf(s1, (float)qb.y, wb.y);
                fb.z = fmaf(s1, (float)qb.z, wb.z);
                fb.w = fmaf(s1, (float)qb.w, wb.w);

                #pragma unroll
                for (int t = 0; t < TOKENS; t++) {
                    float4 xv = xb[t * (IN_F / 4) + c];
                    acc0[t] = fmaf(fa.x, xv.x, acc0[t]);
                    acc0[t] = fmaf(fa.y, xv.y, acc0[t]);
                    acc0[t] = fmaf(fa.z, xv.z, acc0[t]);
                    acc0[t] = fmaf(fa.w, xv.w, acc0[t]);
                    acc1[t] = fmaf(fb.x, xv.x, acc1[t]);
                    acc1[t] = fmaf(fb.y, xv.y, acc1[t]);
                    acc1[t] = fmaf(fb.z, xv.z, acc1[t]);
                    acc1[t] = fmaf(fb.w, xv.w, acc1[t]);
                }
            }

            // Segmented fold: 16 values summed across 32 lanes in 31 shfls.
            // Result on even lanes: r = lane bit4, t = lane bits 3..1.
            float v16[16];
            #pragma unroll
            for (int t = 0; t < TOKENS; t++) { v16[2*t] = acc0[t]; v16[2*t+1] = acc1[t]; }
            #pragma unroll
            for (int i = 0; i < 16; i++) v16[i] += __shfl_xor_sync(0xffffffffu, v16[i], 16);
            float v8[8];
            #pragma unroll
            for (int i = 0; i < 8; i++) v8[i] = (lane & 16) ? v16[2*i+1] : v16[2*i];
            #pragma unroll
            for (int i = 0; i < 8; i++) v8[i] += __shfl_xor_sync(0xffffffffu, v8[i], 8);
            float v4[4];
            #pragma unroll
            for (int i = 0; i < 4; i++) v4[i] = (lane & 8) ? v8[2*i+1] : v8[2*i];
            #pragma unroll
            for (int i = 0; i < 4; i++) v4[i] += __shfl_xor_sync(0xffffffffu, v4[i], 4);
            float v2[2];
            #pragma unroll
            for (int i = 0; i < 2; i++) v2[i] = (lane & 4) ? v4[2*i+1] : v4[2*i];
            #pragma unroll
            for (int i = 0; i < 2; i++) v2[i] += __shfl_xor_sync(0xffffffffu, v2[i], 2);
            v1 = (lane & 2) ? v2[1] : v2[0];
            v1 += __shfl_xor_sync(0xffffffffu, v1, 1);

            // odd warp deposits its 16 partials into this round's buffer
            if (khalf == 1 && !(lane & 1)) {
                buf[lane >> 1] = v1;
            }
        }

        __syncthreads();   // deposit visible (round 0: also orders sumx)
        // WAR on buf is safe: this buffer is rewritten in round r+2, which every
        // warp reaches only after the round r+1 __syncthreads.

        if (active && khalf == 0 && !(lane & 1)) {
            int rr = (lane >> 4) & 1;
            int t  = ((lane >> 3) & 1) | (((lane >> 2) & 1) << 1) | (((lane >> 1) & 1) << 2);
            int o  = o0 + rr;
            float sr = rr ? s1 : s0;
            float total = v1 + buf[lane >> 1];
            out[t * OUT_F + o] = total + fmaf(-sr * zp[o], sumx[t], bias[o]);
        }
    }
}

extern "C" void kernel_launch(void* const* d_in, const int* in_sizes, int n_in,
                              void* d_out, int out_size) {
    const float* x      = (const float*)d_in[0];
    const float* W      = (const float*)d_in[1];
    const int*   Q      = (const int*)d_in[2];
    const float* scales = (const float*)d_in[3];
    const float* zp     = (const float*)d_in[4];
    const float* bias   = (const float*)d_in[5];
    float* out = (float*)d_out;

    cudaFuncSetAttribute(dql_fused, cudaFuncAttributeMaxDynamicSharedMemorySize,
                         SMEM_BYTES);

    dql_fused<<<GRID, THREADS, SMEM_BYTES>>>(x, W, Q, scales, zp, bias, out);
}

// round 13
// speedup vs baseline: 1.2424x; 1.0982x over previous
#include <cuda_runtime.h>

#define IN_F   4096
#define OUT_F  11008
#define TOKENS 8

#define THREADS 512
#define WARPS_PER_BLOCK 16
#define GRID 148

#define NPAIR (OUT_F / 2)                 // 5504 row pairs
#define KCHUNK 2048                       // columns per K-half
#define CHUNK_F4 (KCHUNK / 4)             // 512 float4
#define PAIR_SLOTS (WARPS_PER_BLOCK / 2)  // 8 pairs per block per round
#define PAIRS_PER_ROUND (GRID * PAIR_SLOTS)   // 1184
#define ROUNDS ((NPAIR + PAIRS_PER_ROUND - 1) / PAIRS_PER_ROUND)  // 5

// smem: x[8][4096] | sumx[8] | scratch[ROUNDS][8 slots][2 khalf][16]
#define SCRATCH_FLOATS (ROUNDS * PAIR_SLOTS * 2 * 16)
#define SMEM_FLOATS (TOKENS * IN_F + TOKENS + SCRATCH_FLOATS)
#define SMEM_BYTES  (SMEM_FLOATS * 4)

__global__ __launch_bounds__(THREADS, 1)
void dql_fused(const float* __restrict__ x,
               const float* __restrict__ W,
               const int*   __restrict__ Q,
               const float* __restrict__ scales,
               const float* __restrict__ zp,
               const float* __restrict__ bias,
               float*       __restrict__ out) {
    extern __shared__ float xs[];                 // [TOKENS][IN_F]
    float* sumx    = xs + TOKENS * IN_F;          // [8]
    float* scratch = sumx + TOKENS;               // [ROUNDS][8][2][16]

    // ---- stage x into shared (128 KB), vectorized ----
    {
        const float4* x4 = (const float4*)x;
        float4* xs4w = (float4*)xs;
        #pragma unroll
        for (int i = threadIdx.x; i < TOKENS * IN_F / 4; i += THREADS)
            xs4w[i] = x4[i];
    }
    __syncthreads();

    const int warp  = threadIdx.x >> 5;
    const int lane  = threadIdx.x & 31;

    // ---- in-kernel sumx: warp t reduces token t from shared ----
    // (visibility to consumers ordered by the single final __syncthreads)
    if (warp < TOKENS) {
        float s = 0.f;
        #pragma unroll 4
        for (int i = lane; i < IN_F; i += 32) s += xs[warp * IN_F + i];
        #pragma unroll
        for (int off = 16; off; off >>= 1) s += __shfl_xor_sync(0xffffffffu, s, off);
        if (lane == 0) sumx[warp] = s;
    }

    const int slot  = warp >> 1;        // 0..7 : pair slot within block
    const int khalf = warp & 1;         // 0/1  : K half
    const float4* xs4 = (const float4*)xs;

    // ---- free-running compute: no synchronization between rounds ----
    for (int r = 0; r < ROUNDS; ++r) {
        const int pair = r * PAIRS_PER_ROUND + blockIdx.x * PAIR_SLOTS + slot;
        if (pair < NPAIR) {
            const int o0 = pair << 1;
            const int o1 = o0 + 1;
            const float s0 = scales[o0];
            const float s1 = scales[o1];

            const float4* w0 = (const float4*)(W + (size_t)o0 * IN_F + khalf * KCHUNK);
            const float4* w1 = (const float4*)(W + (size_t)o1 * IN_F + khalf * KCHUNK);
            const int4*   q0 = (const int4*)(Q + (size_t)o0 * IN_F + khalf * KCHUNK);
            const int4*   q1 = (const int4*)(Q + (size_t)o1 * IN_F + khalf * KCHUNK);
            const float4* xb = xs4 + khalf * CHUNK_F4;

            float acc0[TOKENS], acc1[TOKENS];
            #pragma unroll
            for (int t = 0; t < TOKENS; t++) { acc0[t] = 0.f; acc1[t] = 0.f; }

            // 512 float4 per K-half / 32 lanes = 16 iterations; unroll 4
            #pragma unroll 4
            for (int it = 0; it < CHUNK_F4 / 32; ++it) {
                const int c = it * 32 + lane;
                float4 wa = w0[c];
                float4 wb = w1[c];
                int4   qa = q0[c];
                int4   qb = q1[c];

                float4 fa, fb;
                fa.x = fmaf(s0, (float)qa.x, wa.x);
                fa.y = fmaf(s0, (float)qa.y, wa.y);
                fa.z = fmaf(s0, (float)qa.z, wa.z);
                fa.w = fmaf(s0, (float)qa.w, wa.w);
                fb.x = fmaf(s1, (float)qb.x, wb.x);
                fb.y = fmaf(s1, (float)qb.y, wb.y);
                fb.z = fmaf(s1, (float)qb.z, wb.z);
                fb.w = fmaf(s1, (float)qb.w, wb.w);

                #pragma unroll
                for (int t = 0; t < TOKENS; t++) {
                    float4 xv = xb[t * (IN_F / 4) + c];
                    acc0[t] = fmaf(fa.x, xv.x, acc0[t]);
                    acc0[t] = fmaf(fa.y, xv.y, acc0[t]);
                    acc0[t] = fmaf(fa.z, xv.z, acc0[t]);
                    acc0[t] = fmaf(fa.w, xv.w, acc0[t]);
                    acc1[t] = fmaf(fb.x, xv.x, acc1[t]);
                    acc1[t] = fmaf(fb.y, xv.y, acc1[t]);
                    acc1[t] = fmaf(fb.z, xv.z, acc1[t]);
                    acc1[t] = fmaf(fb.w, xv.w, acc1[t]);
                }
            }

            // Segmented fold: 16 values summed across 32 lanes in 31 shfls.
            // After the last xor-1 step, both lanes of each pair hold the total.
            float v16[16];
            #pragma unroll
            for (int t = 0; t < TOKENS; t++) { v16[2*t] = acc0[t]; v16[2*t+1] = acc1[t]; }
            #pragma unroll
            for (int i = 0; i < 16; i++) v16[i] += __shfl_xor_sync(0xffffffffu, v16[i], 16);
            float v8[8];
            #pragma unroll
            for (int i = 0; i < 8; i++) v8[i] = (lane & 16) ? v16[2*i+1] : v16[2*i];
            #pragma unroll
            for (int i = 0; i < 8; i++) v8[i] += __shfl_xor_sync(0xffffffffu, v8[i], 8);
            float v4[4];
            #pragma unroll
            for (int i = 0; i < 4; i++) v4[i] = (lane & 8) ? v8[2*i+1] : v8[2*i];
            #pragma unroll
            for (int i = 0; i < 4; i++) v4[i] += __shfl_xor_sync(0xffffffffu, v4[i], 4);
            float v2[2];
            #pragma unroll
            for (int i = 0; i < 2; i++) v2[i] = (lane & 4) ? v4[2*i+1] : v4[2*i];
            #pragma unroll
            for (int i = 0; i < 2; i++) v2[i] += __shfl_xor_sync(0xffffffffu, v2[i], 2);
            float v1 = (lane & 2) ? v2[1] : v2[0];
            v1 += __shfl_xor_sync(0xffffffffu, v1, 1);

            // both warps deposit their 16 partials; unique scratch per (r,slot,khalf)
            if (!(lane & 1)) {
                scratch[(((r * PAIR_SLOTS) + slot) * 2 + khalf) * 16 + (lane >> 1)] = v1;
            }
        }
    }

    __syncthreads();   // the ONLY combine barrier: all deposits + sumx visible

    // ---- consume: even warp of each slot writes all its rounds' outputs ----
    if (khalf == 0 && !(lane & 1)) {
        const int rr = (lane >> 4) & 1;
        const int t  = ((lane >> 3) & 1) | (((lane >> 2) & 1) << 1) | (((lane >> 1) & 1) << 2);
        const float sx = sumx[t];
        #pragma unroll
        for (int r = 0; r < ROUNDS; ++r) {
            const int pair = r * PAIRS_PER_ROUND + blockIdx.x * PAIR_SLOTS + slot;
            if (pair < NPAIR) {
                const int o = (pair << 1) + rr;
                const float* s2 = scratch + ((r * PAIR_SLOTS) + slot) * 32 + (lane >> 1);
                float total = s2[0] + s2[16];
                out[t * OUT_F + o] = total + fmaf(-scales[o] * zp[o], sx, bias[o]);
            }
        }
    }
}

extern "C" void kernel_launch(void* const* d_in, const int* in_sizes, int n_in,
                              void* d_out, int out_size) {
    const float* x      = (const float*)d_in[0];
    const float* W      = (const float*)d_in[1];
    const int*   Q      = (const int*)d_in[2];
    const float* scales = (const float*)d_in[3];
    const float* zp     = (const float*)d_in[4];
    const float* bias   = (const float*)d_in[5];
    float* out = (float*)d_out;

    cudaFuncSetAttribute(dql_fused, cudaFuncAttributeMaxDynamicSharedMemorySize,
                         SMEM_BYTES);

    dql_fused<<<GRID, THREADS, SMEM_BYTES>>>(x, W, Q, scales, zp, bias, out);
}

// round 14
// speedup vs baseline: 1.2437x; 1.0011x over previous
#include <cuda_runtime.h>

#define IN_F   4096
#define OUT_F  11008
#define TOKENS 8

#define THREADS 512
#define WARPS_PER_BLOCK 16
#define GRID 148

#define NPAIR (OUT_F / 2)                 // 5504 row pairs
#define KCHUNK 2048                       // columns per K-half
#define CHUNK_F4 (KCHUNK / 4)             // 512 float4
#define MAX_LOCAL_PAIRS 38                // ceil(5504/148)
#define MAX_LOCAL_UNITS (2 * MAX_LOCAL_PAIRS)   // 76

// smem: x[8][4096] | sumx[8] | scratch[76][16] | ticket
#define SMEM_FLOATS (TOKENS * IN_F + TOKENS + MAX_LOCAL_UNITS * 16 + 4)
#define SMEM_BYTES  (SMEM_FLOATS * 4)

__global__ __launch_bounds__(THREADS, 1)
void dql_fused(const float* __restrict__ x,
               const float* __restrict__ W,
               const int*   __restrict__ Q,
               const float* __restrict__ scales,
               const float* __restrict__ zp,
               const float* __restrict__ bias,
               float*       __restrict__ out) {
    extern __shared__ float xs[];                 // [TOKENS][IN_F]
    float* sumx    = xs + TOKENS * IN_F;          // [8]
    float* scratch = sumx + TOKENS;               // [76][16]
    int*   ticket  = (int*)(scratch + MAX_LOCAL_UNITS * 16);

    // ---- stage x into shared (128 KB), vectorized; init ticket ----
    if (threadIdx.x == 0) *ticket = 0;
    {
        const float4* x4 = (const float4*)x;
        float4* xs4w = (float4*)xs;
        #pragma unroll
        for (int i = threadIdx.x; i < TOKENS * IN_F / 4; i += THREADS)
            xs4w[i] = x4[i];
    }
    __syncthreads();   // x + ticket visible

    const int warp  = threadIdx.x >> 5;
    const int lane  = threadIdx.x & 31;

    // ---- in-kernel sumx: warp t reduces token t from shared ----
    // (visibility to consumers ordered by the final __syncthreads)
    if (warp < TOKENS) {
        float s = 0.f;
        #pragma unroll 4
        for (int i = lane; i < IN_F; i += 32) s += xs[warp * IN_F + i];
        #pragma unroll
        for (int off = 16; off; off >>= 1) s += __shfl_xor_sync(0xffffffffu, s, off);
        if (lane == 0) sumx[warp] = s;
    }

    // ---- contiguous per-block pair range ----
    const int pair_start = (int)(((long long)blockIdx.x * NPAIR) / GRID);
    const int pair_end   = (int)(((long long)(blockIdx.x + 1) * NPAIR) / GRID);
    const int n_units    = 2 * (pair_end - pair_start);   // 74 or 76

    const float4* xs4 = (const float4*)xs;

    // ---- free-running compute: warps dynamically grab units ----
    for (;;) {
        int ul0 = 0;
        if (lane == 0) ul0 = atomicAdd(ticket, 1);
        const int ul = __shfl_sync(0xffffffffu, ul0, 0);
        if (ul >= n_units) break;

        const int pair  = pair_start + (ul >> 1);
        const int khalf = ul & 1;
        const int o0 = pair << 1;
        const int o1 = o0 + 1;
        const float s0 = scales[o0];
        const float s1 = scales[o1];

        const float4* w0 = (const float4*)(W + (size_t)o0 * IN_F + khalf * KCHUNK);
        const float4* w1 = (const float4*)(W + (size_t)o1 * IN_F + khalf * KCHUNK);
        const int4*   q0 = (const int4*)(Q + (size_t)o0 * IN_F + khalf * KCHUNK);
        const int4*   q1 = (const int4*)(Q + (size_t)o1 * IN_F + khalf * KCHUNK);
        const float4* xb = xs4 + khalf * CHUNK_F4;

        float acc0[TOKENS], acc1[TOKENS];
        #pragma unroll
        for (int t = 0; t < TOKENS; t++) { acc0[t] = 0.f; acc1[t] = 0.f; }

        // 512 float4 per K-half / 32 lanes = 16 iterations; unroll 4
        #pragma unroll 4
        for (int it = 0; it < CHUNK_F4 / 32; ++it) {
            const int c = it * 32 + lane;
            float4 wa = w0[c];
            float4 wb = w1[c];
            int4   qa = q0[c];
            int4   qb = q1[c];

            float4 fa, fb;
            fa.x = fmaf(s0, (float)qa.x, wa.x);
            fa.y = fmaf(s0, (float)qa.y, wa.y);
            fa.z = fmaf(s0, (float)qa.z, wa.z);
            fa.w = fmaf(s0, (float)qa.w, wa.w);
            fb.x = fmaf(s1, (float)qb.x, wb.x);
            fb.y = fmaf(s1, (float)qb.y, wb.y);
            fb.z = fmaf(s1, (float)qb.z, wb.z);
            fb.w = fmaf(s1, (float)qb.w, wb.w);

            #pragma unroll
            for (int t = 0; t < TOKENS; t++) {
                float4 xv = xb[t * (IN_F / 4) + c];
                acc0[t] = fmaf(fa.x, xv.x, acc0[t]);
                acc0[t] = fmaf(fa.y, xv.y, acc0[t]);
                acc0[t] = fmaf(fa.z, xv.z, acc0[t]);
                acc0[t] = fmaf(fa.w, xv.w, acc0[t]);
                acc1[t] = fmaf(fb.x, xv.x, acc1[t]);
                acc1[t] = fmaf(fb.y, xv.y, acc1[t]);
                acc1[t] = fmaf(fb.z, xv.z, acc1[t]);
                acc1[t] = fmaf(fb.w, xv.w, acc1[t]);
            }
        }

        // Segmented fold: 16 values summed across 32 lanes in 31 shfls.
        float v16[16];
        #pragma unroll
        for (int t = 0; t < TOKENS; t++) { v16[2*t] = acc0[t]; v16[2*t+1] = acc1[t]; }
        #pragma unroll
        for (int i = 0; i < 16; i++) v16[i] += __shfl_xor_sync(0xffffffffu, v16[i], 16);
        float v8[8];
        #pragma unroll
        for (int i = 0; i < 8; i++) v8[i] = (lane & 16) ? v16[2*i+1] : v16[2*i];
        #pragma unroll
        for (int i = 0; i < 8; i++) v8[i] += __shfl_xor_sync(0xffffffffu, v8[i], 8);
        float v4[4];
        #pragma unroll
        for (int i = 0; i < 4; i++) v4[i] = (lane & 8) ? v8[2*i+1] : v8[2*i];
        #pragma unroll
        for (int i = 0; i < 4; i++) v4[i] += __shfl_xor_sync(0xffffffffu, v4[i], 4);
        float v2[2];
        #pragma unroll
        for (int i = 0; i < 2; i++) v2[i] = (lane & 4) ? v4[2*i+1] : v4[2*i];
        #pragma unroll
        for (int i = 0; i < 2; i++) v2[i] += __shfl_xor_sync(0xffffffffu, v2[i], 2);
        float v1 = (lane & 2) ? v2[1] : v2[0];
        v1 += __shfl_xor_sync(0xffffffffu, v1, 1);

        // deposit 16 partials; unique scratch row per local unit
        if (!(lane & 1)) {
            scratch[ul * 16 + (lane >> 1)] = v1;
        }
    }

    __syncthreads();   // the ONLY combine barrier: all deposits + sumx visible

    // ---- consume: all 16 warps split the block's pairs ----
    {
        const int npl = pair_end - pair_start;
        const int rr = (lane >> 4) & 1;
        const int t  = ((lane >> 3) & 1) | (((lane >> 2) & 1) << 1) | (((lane >> 1) & 1) << 2);
        const float sx = sumx[t];
        if (!(lane & 1)) {
            for (int pl = warp; pl < npl; pl += WARPS_PER_BLOCK) {
                const int o = ((pair_start + pl) << 1) + rr;
                float total = scratch[(2 * pl) * 16 + (lane >> 1)]
                            + scratch[(2 * pl + 1) * 16 + (lane >> 1)];
                out[t * OUT_F + o] = total + fmaf(-scales[o] * zp[o], sx, bias[o]);
            }
        }
    }
}

extern "C" void kernel_launch(void* const* d_in, const int* in_sizes, int n_in,
                              void* d_out, int out_size) {
    const float* x      = (const float*)d_in[0];
    const float* W      = (const float*)d_in[1];
    const int*   Q      = (const int*)d_in[2];
    const float* scales = (const float*)d_in[3];
    const float* zp     = (const float*)d_in[4];
    const float* bias   = (const float*)d_in[5];
    float* out = (float*)d_out;

    cudaFuncSetAttribute(dql_fused, cudaFuncAttributeMaxDynamicSharedMemorySize,
                         SMEM_BYTES);

    dql_fused<<<GRID, THREADS, SMEM_BYTES>>>(x, W, Q, scales, zp, bias, out);
}